// round 1
// baseline (speedup 1.0000x reference)
#include <cuda_runtime.h>

// Local cost volume (SpatialCorrelationSampler, kernel_size=1, patch 9x9):
// out[b, p, y, x] = sum_c t1[b,c,y,x] * t2[b,c,y+di,x+dj],  p=(di+4)*9+(dj+4)
// Shapes: t1,t2 [4,128,128,256] f32 -> out [4,81,128,256] f32.

#define BB 4
#define CH 128
#define HH 128
#define WW 256
#define MD 4
#define DD 9           // 2*MD+1
#define CC 4           // channels per smem chunk
#define T2W (WW + 2*MD) // 264 floats per halo row (multiple of 4 -> 16B aligned)
#define NTHREADS 288   // 9 warps; warp w handles displacement row di = w-4

__global__ __launch_bounds__(NTHREADS, 2)
void corr_volume_kernel(const float* __restrict__ t1,
                        const float* __restrict__ t2,
                        float* __restrict__ out)
{
    __shared__ float s_t1[CC][WW];
    __shared__ float s_t2[CC][DD][T2W];

    const int tid  = threadIdx.x;
    const int wid  = tid >> 5;     // 0..8 : di row index
    const int lane = tid & 31;     // 32 lanes x 8 px = 256 px (full width)
    const int blk  = blockIdx.x;   // 0..511
    const int batch = blk >> 7;    // / HH
    const int y     = blk & (HH - 1);

    const float* t1row = t1 + ((size_t)batch * CH) * (HH * WW) + (size_t)y * WW;
    const float* t2img = t2 + ((size_t)batch * CH) * (HH * WW);

    // 9 dj x 8 px accumulators per thread
    float acc[DD][8];
    #pragma unroll
    for (int d = 0; d < DD; d++)
        #pragma unroll
        for (int k = 0; k < 8; k++)
            acc[d][k] = 0.0f;

    const int x0 = lane * 8;

    for (int c0 = 0; c0 < CH; c0 += CC) {
        __syncthreads();   // protect smem from previous iteration's readers

        // ---- load t1 chunk: CC rows of 256 floats ----
        #pragma unroll
        for (int i = tid; i < CC * WW; i += NTHREADS) {
            int cc = i >> 8;            // / WW (WW = 256)
            int x  = i & (WW - 1);
            s_t1[cc][x] = t1row[(size_t)(c0 + cc) * (HH * WW) + x];
        }

        // ---- load t2 chunk: CC x 9 halo rows x 264 cols (zero padded) ----
        for (int i = tid; i < CC * DD * T2W; i += NTHREADS) {
            int cc  = i / (DD * T2W);
            int rem = i - cc * (DD * T2W);
            int r   = rem / T2W;
            int col = rem - r * T2W;
            int gy = y + r - MD;
            int gx = col - MD;
            float v = 0.0f;
            if ((unsigned)gy < (unsigned)HH && (unsigned)gx < (unsigned)WW)
                v = t2img[(size_t)(c0 + cc) * (HH * WW) + (size_t)gy * WW + gx];
            s_t2[cc][r][col] = v;
        }

        __syncthreads();

        // ---- accumulate ----
        #pragma unroll
        for (int cc = 0; cc < CC; cc++) {
            float4 a0 = *(const float4*)&s_t1[cc][x0];
            float4 a1 = *(const float4*)&s_t1[cc][x0 + 4];
            float t1v[8] = {a0.x, a0.y, a0.z, a0.w, a1.x, a1.y, a1.z, a1.w};

            // sliding window of 16 t2 values: smem cols x0 .. x0+15
            float w[16];
            #pragma unroll
            for (int j = 0; j < 4; j++) {
                float4 v = *(const float4*)&s_t2[cc][wid][x0 + 4 * j];
                w[4*j + 0] = v.x; w[4*j + 1] = v.y;
                w[4*j + 2] = v.z; w[4*j + 3] = v.w;
            }

            #pragma unroll
            for (int dj = 0; dj < DD; dj++)
                #pragma unroll
                for (int k = 0; k < 8; k++)
                    acc[dj][k] = fmaf(t1v[k], w[k + dj], acc[dj][k]);
        }
    }

    // ---- write out: p = wid*9 + dj ----
    const size_t plane = (size_t)HH * WW;
    size_t obase = (((size_t)batch * 81 + (size_t)wid * DD) * HH + y) * WW + x0;
    #pragma unroll
    for (int dj = 0; dj < DD; dj++) {
        float4 o0 = make_float4(acc[dj][0], acc[dj][1], acc[dj][2], acc[dj][3]);
        float4 o1 = make_float4(acc[dj][4], acc[dj][5], acc[dj][6], acc[dj][7]);
        *(float4*)&out[obase + dj * plane]     = o0;
        *(float4*)&out[obase + dj * plane + 4] = o1;
    }
}

extern "C" void kernel_launch(void* const* d_in, const int* in_sizes, int n_in,
                              void* d_out, int out_size)
{
    const float* t1 = (const float*)d_in[0];
    const float* t2 = (const float*)d_in[1];
    float* out = (float*)d_out;
    corr_volume_kernel<<<BB * HH, NTHREADS>>>(t1, t2, out);
}

// round 2
// speedup vs baseline: 1.4153x; 1.4153x over previous
#include <cuda_runtime.h>

// Local cost volume (SpatialCorrelationSampler, kernel_size=1, patch 9x9):
// out[b, p, y, x] = sum_c t1[b,c,y,x] * t2[b,c,y+di,x+dj],  p=(di+4)*9+(dj+4)
// Shapes: t1,t2 [4,128,128,256] f32 -> out [4,81,128,256] f32.
//
// Block = one (batch, y). 9 warps; warp w owns displacement row di = w-4.
// Lane owns 8 consecutive x. Packed fma.rn.f32x2 accumulators (36 x b64).
// Loads are warp-structured: warp w fills t2 halo row r=w (warp-uniform
// validity), warps 0..3 fill t1 channel rows. No division, no per-element
// bounds checks, pointers hoisted.

#define CH 128
#define HH 128
#define WW 256
#define MD 4
#define DD 9
#define CC 4
#define T2W (WW + 2*MD)   // 264
#define HW (HH*WW)
#define NTHREADS 288

typedef unsigned long long u64;

__device__ __forceinline__ u64 pk(float lo, float hi) {
    u64 r; asm("mov.b64 %0, {%1,%2};" : "=l"(r) : "f"(lo), "f"(hi)); return r;
}
__device__ __forceinline__ void fma2(u64 &d, u64 a, u64 b) {
    asm("fma.rn.f32x2 %0, %1, %2, %0;" : "+l"(d) : "l"(a), "l"(b));
}
__device__ __forceinline__ float2 upk(u64 v) {
    float lo, hi; asm("mov.b64 {%0,%1}, %2;" : "=f"(lo), "=f"(hi) : "l"(v));
    return make_float2(lo, hi);
}

__global__ __launch_bounds__(NTHREADS, 2)
void corr_volume_kernel(const float* __restrict__ t1,
                        const float* __restrict__ t2,
                        float* __restrict__ out)
{
    __shared__ float s_t1[CC][WW];
    __shared__ float s_t2[CC][DD][T2W];

    const int tid   = threadIdx.x;
    const int wid   = tid >> 5;          // 0..8
    const int lane  = tid & 31;
    const int batch = blockIdx.x >> 7;
    const int y     = blockIdx.x & (HH - 1);

    // t2 loader: this warp fills halo row r = wid  ->  gy = y + wid - MD
    const int gy = y + wid - MD;
    const bool valid = (unsigned)gy < (unsigned)HH;     // warp-uniform
    const float* t2p = t2 + (size_t)batch * CH * HW + (size_t)(valid ? gy : 0) * WW;
    // t1 loader: warps 0..3 fill channel row cc = wid
    const float* t1p = t1 + (size_t)batch * CH * HW + (size_t)y * WW;

    u64 acc[DD][4];
    #pragma unroll
    for (int d = 0; d < DD; d++) {
        acc[d][0] = 0ull; acc[d][1] = 0ull; acc[d][2] = 0ull; acc[d][3] = 0ull;
    }

    const int x0 = lane * 8;
    const float4 zero4 = make_float4(0.f, 0.f, 0.f, 0.f);

    for (int c0 = 0; c0 < CH; c0 += CC) {
        __syncthreads();   // previous chunk's readers done

        // ---- t1: warps 0..3, channel row c0+wid, 64 float4 ----
        if (wid < CC) {
            const float* src = t1p + (size_t)(c0 + wid) * HW;
            *(float4*)&s_t1[wid][4 * lane]        = *(const float4*)&src[4 * lane];
            *(float4*)&s_t1[wid][4 * (lane + 32)] = *(const float4*)&src[4 * (lane + 32)];
        }

        // ---- t2: every warp fills its halo row for CC channels ----
        #pragma unroll
        for (int cc = 0; cc < CC; cc++) {
            float* drow = &s_t2[cc][wid][0];
            if (valid) {
                const float* src = t2p + (size_t)(c0 + cc) * HW;
                *(float4*)&drow[4 + 4 * lane]        = *(const float4*)&src[4 * lane];
                *(float4*)&drow[4 + 4 * (lane + 32)] = *(const float4*)&src[4 * (lane + 32)];
                if (lane == 0) *(float4*)&drow[0]   = zero4;   // cols 0..3
                if (lane == 1) *(float4*)&drow[260] = zero4;   // cols 260..263
            } else {
                *(float4*)&drow[4 * lane]        = zero4;      // cols 0..127
                *(float4*)&drow[4 * (lane + 32)] = zero4;      // cols 128..255
                if (lane == 0) *(float4*)&drow[256] = zero4;
                if (lane == 1) *(float4*)&drow[260] = zero4;
            }
        }

        __syncthreads();

        // ---- accumulate: per cc, 36 packed FMAs ----
        #pragma unroll
        for (int cc = 0; cc < CC; cc++) {
            float4 a0 = *(const float4*)&s_t1[cc][x0];
            float4 a1 = *(const float4*)&s_t1[cc][x0 + 4];
            u64 A0 = pk(a0.x, a0.y), A1 = pk(a0.z, a0.w);
            u64 A2 = pk(a1.x, a1.y), A3 = pk(a1.z, a1.w);

            float4 v0 = *(const float4*)&s_t2[cc][wid][x0];
            float4 v1 = *(const float4*)&s_t2[cc][wid][x0 + 4];
            float4 v2 = *(const float4*)&s_t2[cc][wid][x0 + 8];
            float4 v3 = *(const float4*)&s_t2[cc][wid][x0 + 12];

            // aligned pairs P[i] = (w[2i], w[2i+1])
            u64 P[8];
            P[0] = pk(v0.x, v0.y); P[1] = pk(v0.z, v0.w);
            P[2] = pk(v1.x, v1.y); P[3] = pk(v1.z, v1.w);
            P[4] = pk(v2.x, v2.y); P[5] = pk(v2.z, v2.w);
            P[6] = pk(v3.x, v3.y); P[7] = pk(v3.z, v3.w);
            // odd pairs Q[i] = (w[2i+1], w[2i+2])
            u64 Q[7];
            Q[0] = pk(v0.y, v0.z); Q[1] = pk(v0.w, v1.x);
            Q[2] = pk(v1.y, v1.z); Q[3] = pk(v1.w, v2.x);
            Q[4] = pk(v2.y, v2.z); Q[5] = pk(v2.w, v3.x);
            Q[6] = pk(v3.y, v3.z);

            #pragma unroll
            for (int dj = 0; dj < DD; dj++) {
                const int h = dj >> 1;
                if ((dj & 1) == 0) {
                    fma2(acc[dj][0], A0, P[h + 0]);
                    fma2(acc[dj][1], A1, P[h + 1]);
                    fma2(acc[dj][2], A2, P[h + 2]);
                    fma2(acc[dj][3], A3, P[h + 3]);
                } else {
                    fma2(acc[dj][0], A0, Q[h + 0]);
                    fma2(acc[dj][1], A1, Q[h + 1]);
                    fma2(acc[dj][2], A2, Q[h + 2]);
                    fma2(acc[dj][3], A3, Q[h + 3]);
                }
            }
        }
    }

    // ---- write out: p = wid*9 + dj ----
    size_t obase = (((size_t)batch * 81 + (size_t)wid * DD) * HH + y) * WW + x0;
    #pragma unroll
    for (int dj = 0; dj < DD; dj++) {
        float2 p0 = upk(acc[dj][0]), p1 = upk(acc[dj][1]);
        float2 p2 = upk(acc[dj][2]), p3 = upk(acc[dj][3]);
        *(float4*)&out[obase + (size_t)dj * HW]     = make_float4(p0.x, p0.y, p1.x, p1.y);
        *(float4*)&out[obase + (size_t)dj * HW + 4] = make_float4(p2.x, p2.y, p3.x, p3.y);
    }
}

extern "C" void kernel_launch(void* const* d_in, const int* in_sizes, int n_in,
                              void* d_out, int out_size)
{
    const float* t1 = (const float*)d_in[0];
    const float* t2 = (const float*)d_in[1];
    float* out = (float*)d_out;
    corr_volume_kernel<<<4 * HH, NTHREADS>>>(t1, t2, out);
}

// round 3
// speedup vs baseline: 2.1144x; 1.4939x over previous
#include <cuda_runtime.h>

// Local cost volume (SpatialCorrelationSampler, kernel_size=1, patch 9x9):
// out[b, p, y, x] = sum_c t1[b,c,y,x] * t2[b,c,y+di,x+dj],  p=(di+4)*9+(dj+4)
// Shapes: t1,t2 [4,128,128,256] f32 -> out [4,81,128,256] f32.
//
// Block = one (batch, y). 9 warps; warp w owns displacement row di = w-4.
// Lane owns 8 consecutive x. Packed fma.rn.f32x2 accumulators.
// Double-buffered smem filled with cp.async.cg (LDGSTS): chunk n+1 streams
// in while chunk n computes. Halo padding zeroed once before the loop.

#define CH 128
#define HH 128
#define WW 256
#define MD 4
#define DD 9
#define CC 4
#define T2W (WW + 2*MD)   // 264
#define HW (HH*WW)
#define NTHREADS 288
#define NCHUNK (CH / CC)  // 32

// dynamic smem layout (floats):
//   s_t1: [2][CC][WW]        = 2048
//   s_t2: [2][CC][DD][T2W]   = 19008
#define S_T1_FLOATS (2 * CC * WW)
#define S_T2_FLOATS (2 * CC * DD * T2W)
#define SMEM_BYTES ((S_T1_FLOATS + S_T2_FLOATS) * 4)

typedef unsigned long long u64;

__device__ __forceinline__ u64 pk(float lo, float hi) {
    u64 r; asm("mov.b64 %0, {%1,%2};" : "=l"(r) : "f"(lo), "f"(hi)); return r;
}
__device__ __forceinline__ void fma2(u64 &d, u64 a, u64 b) {
    asm("fma.rn.f32x2 %0, %1, %2, %0;" : "+l"(d) : "l"(a), "l"(b));
}
__device__ __forceinline__ float2 upk(u64 v) {
    float lo, hi; asm("mov.b64 {%0,%1}, %2;" : "=f"(lo), "=f"(hi) : "l"(v));
    return make_float2(lo, hi);
}
__device__ __forceinline__ void cpasync16(unsigned smem_addr, const void* gptr) {
    asm volatile("cp.async.cg.shared.global [%0], [%1], 16;" ::
                 "r"(smem_addr), "l"(gptr));
}

__global__ __launch_bounds__(NTHREADS, 2)
void corr_volume_kernel(const float* __restrict__ t1,
                        const float* __restrict__ t2,
                        float* __restrict__ out)
{
    extern __shared__ float sm[];
    float* s_t1 = sm;                    // [2][CC][WW]
    float* s_t2 = sm + S_T1_FLOATS;      // [2][CC][DD][T2W]

    const int tid   = threadIdx.x;
    const int wid   = tid >> 5;          // 0..8
    const int lane  = tid & 31;
    const int batch = blockIdx.x >> 7;
    const int y     = blockIdx.x & (HH - 1);

    const int gy = y + wid - MD;                       // this warp's t2 halo row
    const bool valid = (unsigned)gy < (unsigned)HH;    // warp-uniform
    const float* t2p = t2 + (size_t)batch * CH * HW + (size_t)(valid ? gy : 0) * WW;
    const float* t1p = t1 + (size_t)batch * CH * HW + (size_t)y * WW;

    // ---- one-time zero of constant padding regions (both buffers) ----
    // invalid halo rows: whole row stays zero; valid rows: cols 0..3, 260..263
    {
        const float4 z = make_float4(0.f, 0.f, 0.f, 0.f);
        #pragma unroll
        for (int buf = 0; buf < 2; buf++) {
            #pragma unroll
            for (int cc = 0; cc < CC; cc++) {
                float* row = s_t2 + ((buf * CC + cc) * DD + wid) * T2W;
                if (valid) {
                    if (lane == 0) *(float4*)&row[0]   = z;
                    if (lane == 1) *(float4*)&row[260] = z;
                } else {
                    *(float4*)&row[4 * lane]        = z;   // 0..127
                    *(float4*)&row[4 * (lane + 32)] = z;   // 128..255
                    if (lane == 0) *(float4*)&row[256] = z;
                    if (lane == 1) *(float4*)&row[260] = z;
                }
            }
        }
    }
    __syncthreads();

    u64 acc[DD][4];
    #pragma unroll
    for (int d = 0; d < DD; d++) {
        acc[d][0] = 0ull; acc[d][1] = 0ull; acc[d][2] = 0ull; acc[d][3] = 0ull;
    }

    const int x0 = lane * 8;

    // precompute shared addresses for this thread's copy targets
    unsigned t1dst = 0;
    if (wid < CC)
        t1dst = (unsigned)__cvta_generic_to_shared(&s_t1[wid * WW + 4 * lane]);
    unsigned t2dst = (unsigned)__cvta_generic_to_shared(
        s_t2 + (0 * CC * DD + wid) * T2W + 4 + 4 * lane);

    // issue async copies for chunk (c0), into buffer buf
    auto issue = [&](int c0, int buf) {
        // t1: warps 0..3 copy channel row c0+wid (2 x 16B per lane)
        if (wid < CC) {
            const float* src = t1p + (size_t)(c0 + wid) * HW;
            unsigned d0 = t1dst + buf * (CC * WW * 4);
            cpasync16(d0,        &src[4 * lane]);
            cpasync16(d0 + 512,  &src[4 * (lane + 32)]);   // +128 floats
        }
        // t2: every valid warp copies its halo row for CC channels
        if (valid) {
            unsigned dbase = t2dst + buf * (CC * DD * T2W * 4);
            #pragma unroll
            for (int cc = 0; cc < CC; cc++) {
                const float* src = t2p + (size_t)(c0 + cc) * HW;
                unsigned d0 = dbase + cc * (DD * T2W * 4);
                cpasync16(d0,        &src[4 * lane]);
                cpasync16(d0 + 512,  &src[4 * (lane + 32)]);
            }
        }
        asm volatile("cp.async.commit_group;");
    };

    issue(0, 0);

    for (int it = 0; it < NCHUNK; it++) {
        const int buf = it & 1;
        if (it + 1 < NCHUNK) {
            issue((it + 1) * CC, buf ^ 1);
            asm volatile("cp.async.wait_group 1;");
        } else {
            asm volatile("cp.async.wait_group 0;");
        }
        __syncthreads();

        const float* b_t1 = s_t1 + buf * (CC * WW);
        const float* b_t2 = s_t2 + buf * (CC * DD * T2W);

        #pragma unroll
        for (int cc = 0; cc < CC; cc++) {
            float4 a0 = *(const float4*)&b_t1[cc * WW + x0];
            float4 a1 = *(const float4*)&b_t1[cc * WW + x0 + 4];
            u64 A0 = pk(a0.x, a0.y), A1 = pk(a0.z, a0.w);
            u64 A2 = pk(a1.x, a1.y), A3 = pk(a1.z, a1.w);

            const float* trow = b_t2 + (cc * DD + wid) * T2W + x0;
            float4 v0 = *(const float4*)&trow[0];
            float4 v1 = *(const float4*)&trow[4];
            float4 v2 = *(const float4*)&trow[8];
            float4 v3 = *(const float4*)&trow[12];

            u64 P[8];
            P[0] = pk(v0.x, v0.y); P[1] = pk(v0.z, v0.w);
            P[2] = pk(v1.x, v1.y); P[3] = pk(v1.z, v1.w);
            P[4] = pk(v2.x, v2.y); P[5] = pk(v2.z, v2.w);
            P[6] = pk(v3.x, v3.y); P[7] = pk(v3.z, v3.w);
            u64 Q[7];
            Q[0] = pk(v0.y, v0.z); Q[1] = pk(v0.w, v1.x);
            Q[2] = pk(v1.y, v1.z); Q[3] = pk(v1.w, v2.x);
            Q[4] = pk(v2.y, v2.z); Q[5] = pk(v2.w, v3.x);
            Q[6] = pk(v3.y, v3.z);

            #pragma unroll
            for (int dj = 0; dj < DD; dj++) {
                const int h = dj >> 1;
                if ((dj & 1) == 0) {
                    fma2(acc[dj][0], A0, P[h + 0]);
                    fma2(acc[dj][1], A1, P[h + 1]);
                    fma2(acc[dj][2], A2, P[h + 2]);
                    fma2(acc[dj][3], A3, P[h + 3]);
                } else {
                    fma2(acc[dj][0], A0, Q[h + 0]);
                    fma2(acc[dj][1], A1, Q[h + 1]);
                    fma2(acc[dj][2], A2, Q[h + 2]);
                    fma2(acc[dj][3], A3, Q[h + 3]);
                }
            }
        }
        __syncthreads();   // all readers done before buffer is refilled
    }

    // ---- write out: p = wid*9 + dj ----
    size_t obase = (((size_t)batch * 81 + (size_t)wid * DD) * HH + y) * WW + x0;
    #pragma unroll
    for (int dj = 0; dj < DD; dj++) {
        float2 p0 = upk(acc[dj][0]), p1 = upk(acc[dj][1]);
        float2 p2 = upk(acc[dj][2]), p3 = upk(acc[dj][3]);
        *(float4*)&out[obase + (size_t)dj * HW]     = make_float4(p0.x, p0.y, p1.x, p1.y);
        *(float4*)&out[obase + (size_t)dj * HW + 4] = make_float4(p2.x, p2.y, p3.x, p3.y);
    }
}

extern "C" void kernel_launch(void* const* d_in, const int* in_sizes, int n_in,
                              void* d_out, int out_size)
{
    const float* t1 = (const float*)d_in[0];
    const float* t2 = (const float*)d_in[1];
    float* out = (float*)d_out;
    cudaFuncSetAttribute(corr_volume_kernel,
                         cudaFuncAttributeMaxDynamicSharedMemorySize, SMEM_BYTES);
    corr_volume_kernel<<<4 * HH, NTHREADS, SMEM_BYTES>>>(t1, t2, out);
}

// round 4
// speedup vs baseline: 3.4448x; 1.6292x over previous
#include <cuda_runtime.h>

// Local cost volume (SpatialCorrelationSampler, kernel_size=1, patch 9x9):
// out[b, p, y, x] = sum_c t1[b,c,y,x] * t2[b,c,y+di,x+dj],  p=(di+4)*9+(dj+4)
// Shapes: t1,t2 [4,128,128,256] f32 -> out [4,81,128,256] f32.
//
// Block = one (batch, y, x-tile of 128). 9 warps; warp w owns di = w-4.
// Lane owns 4 consecutive x -> 9 dj x 2 u64 packed accumulators (36 regs).
// 3 CTAs/SM (reg-capped via launch_bounds), conflict-free 16B-stride LDS,
// cp.async double buffer with a single barrier per channel chunk.

#define CH 128
#define HH 128
#define WW 256
#define MD 4
#define DD 9
#define CC 4
#define XT 128            // x-tile width
#define T2C 136           // halo cols per tile (XT + 2*MD)
#define HW (HH*WW)
#define NTHREADS 288
#define NCHUNK (CH / CC)  // 32

#define S_T1_FLOATS (2 * CC * XT)        // 1024
#define S_T2_FLOATS (2 * CC * DD * T2C)  // 9792
#define SMEM_BYTES ((S_T1_FLOATS + S_T2_FLOATS) * 4)

typedef unsigned long long u64;

__device__ __forceinline__ u64 pk(float lo, float hi) {
    u64 r; asm("mov.b64 %0, {%1,%2};" : "=l"(r) : "f"(lo), "f"(hi)); return r;
}
__device__ __forceinline__ void fma2(u64 &d, u64 a, u64 b) {
    asm("fma.rn.f32x2 %0, %1, %2, %0;" : "+l"(d) : "l"(a), "l"(b));
}
__device__ __forceinline__ float2 upk(u64 v) {
    float lo, hi; asm("mov.b64 {%0,%1}, %2;" : "=f"(lo), "=f"(hi) : "l"(v));
    return make_float2(lo, hi);
}
__device__ __forceinline__ void cpasync16(unsigned smem_addr, const void* gptr) {
    asm volatile("cp.async.cg.shared.global [%0], [%1], 16;" ::
                 "r"(smem_addr), "l"(gptr));
}

__global__ __launch_bounds__(NTHREADS, 3)
void corr_volume_kernel(const float* __restrict__ t1,
                        const float* __restrict__ t2,
                        float* __restrict__ out)
{
    extern __shared__ float sm[];
    float* s_t1 = sm;                    // [2][CC][XT]
    float* s_t2 = sm + S_T1_FLOATS;      // [2][CC][DD][T2C]

    const int tid   = threadIdx.x;
    const int wid   = tid >> 5;          // 0..8 : di row
    const int lane  = tid & 31;
    const int blk   = blockIdx.x;        // 0..1023
    const int xt    = blk & 1;
    const int y     = (blk >> 1) & (HH - 1);
    const int batch = blk >> 8;
    const int x0    = xt * XT;

    const int gy = y + wid - MD;
    const bool vrow = (unsigned)gy < (unsigned)HH;    // warp-uniform
    const float* t2row = t2 + (size_t)batch * CH * HW + (size_t)(vrow ? gy : 0) * WW;
    const float* t1row = t1 + (size_t)batch * CH * HW + (size_t)y * WW;

    // halo chunk geometry: chunk h covers smem cols [4h,4h+4), gx = x0-4+4h.
    // valid chunks: [lo, lo+33); exactly one padding chunk per row.
    const int lo = (xt == 0) ? 1 : 0;

    // ---- one-time zero of constant padding (both buffers) ----
    {
        const float4 z = make_float4(0.f, 0.f, 0.f, 0.f);
        #pragma unroll
        for (int buf = 0; buf < 2; buf++)
            #pragma unroll
            for (int cc = 0; cc < CC; cc++) {
                float* row = s_t2 + ((buf * CC + cc) * DD + wid) * T2C;
                if (vrow) {
                    int hpad = (xt == 0) ? 0 : 33;
                    if (lane == 0) *(float4*)&row[4 * hpad] = z;
                } else {
                    *(float4*)&row[4 * lane] = z;               // chunks 0..31
                    if (lane < 2) *(float4*)&row[4 * (32 + lane)] = z;
                }
            }
    }

    u64 acc[DD][2];
    #pragma unroll
    for (int d = 0; d < DD; d++) { acc[d][0] = 0ull; acc[d][1] = 0ull; }

    const int xl = lane * 4;   // within-tile x offset for compute

    // copy target addresses (buffer 0)
    unsigned t1dst = (unsigned)__cvta_generic_to_shared(&s_t1[wid * XT + xl]);
    unsigned t2dst = (unsigned)__cvta_generic_to_shared(
        s_t2 + (size_t)wid * T2C + 4 * (lo + lane));
    unsigned t2dst2 = (unsigned)__cvta_generic_to_shared(
        s_t2 + (size_t)wid * T2C + 4 * (lo + 32));

    auto issue = [&](int c0, int buf) {
        if (wid < CC) {
            const float* src = t1row + (size_t)(c0 + wid) * HW + x0;
            cpasync16(t1dst + buf * (CC * XT * 4), &src[xl]);
        }
        if (vrow) {
            const int gx0 = x0 - 4 + 4 * lo;
            #pragma unroll
            for (int cc = 0; cc < CC; cc++) {
                const float* src = t2row + (size_t)(c0 + cc) * HW + gx0;
                unsigned off = (unsigned)((buf * CC + cc) * (DD * T2C) * 4);
                cpasync16(t2dst + off, &src[4 * lane]);
                if (lane == 0) cpasync16(t2dst2 + off, &src[128]);
            }
        }
        asm volatile("cp.async.commit_group;");
    };

    issue(0, 0);
    // ensure one-time zero stores are also visible before first compute
    for (int it = 0; it < NCHUNK; it++) {
        const int buf = it & 1;
        asm volatile("cp.async.wait_group 0;");
        __syncthreads();                       // chunk `it` visible; buf^1 free
        if (it + 1 < NCHUNK) issue((it + 1) * CC, buf ^ 1);

        const float* b_t1 = s_t1 + buf * (CC * XT);
        const float* b_t2 = s_t2 + buf * (CC * DD * T2C);

        #pragma unroll
        for (int cc = 0; cc < CC; cc++) {
            float4 a = *(const float4*)&b_t1[cc * XT + xl];
            u64 A0 = pk(a.x, a.y), A1 = pk(a.z, a.w);

            const float* tr = &b_t2[(cc * DD + wid) * T2C + xl];
            float4 v0 = *(const float4*)&tr[0];
            float4 v1 = *(const float4*)&tr[4];
            float4 v2 = *(const float4*)&tr[8];

            u64 P[6];
            P[0] = pk(v0.x, v0.y); P[1] = pk(v0.z, v0.w);
            P[2] = pk(v1.x, v1.y); P[3] = pk(v1.z, v1.w);
            P[4] = pk(v2.x, v2.y); P[5] = pk(v2.z, v2.w);
            u64 Q[5];
            Q[0] = pk(v0.y, v0.z); Q[1] = pk(v0.w, v1.x);
            Q[2] = pk(v1.y, v1.z); Q[3] = pk(v1.w, v2.x);
            Q[4] = pk(v2.y, v2.z);

            #pragma unroll
            for (int dj = 0; dj < DD; dj++) {
                const int h = dj >> 1;
                if ((dj & 1) == 0) {
                    fma2(acc[dj][0], A0, P[h + 0]);
                    fma2(acc[dj][1], A1, P[h + 1]);
                } else {
                    fma2(acc[dj][0], A0, Q[h + 0]);
                    fma2(acc[dj][1], A1, Q[h + 1]);
                }
            }
        }
    }

    // ---- write out: p = wid*9 + dj ----
    size_t obase = (((size_t)batch * 81 + (size_t)wid * DD) * HH + y) * WW + x0 + xl;
    #pragma unroll
    for (int dj = 0; dj < DD; dj++) {
        float2 p0 = upk(acc[dj][0]), p1 = upk(acc[dj][1]);
        *(float4*)&out[obase + (size_t)dj * HW] = make_float4(p0.x, p0.y, p1.x, p1.y);
    }
}

extern "C" void kernel_launch(void* const* d_in, const int* in_sizes, int n_in,
                              void* d_out, int out_size)
{
    const float* t1 = (const float*)d_in[0];
    const float* t2 = (const float*)d_in[1];
    float* out = (float*)d_out;
    cudaFuncSetAttribute(corr_volume_kernel,
                         cudaFuncAttributeMaxDynamicSharedMemorySize, SMEM_BYTES);
    corr_volume_kernel<<<2 * 4 * HH, NTHREADS, SMEM_BYTES>>>(t1, t2, out);
}